// round 3
// baseline (speedup 1.0000x reference)
#include <cuda_runtime.h>
#include <math.h>

// Shapes (fixed by the problem):
//   x  : [B=8, C=128, D=4, H=128, W=128]  -> 67,108,864 fp32 (256 MB)
//   w1 : [C, C] row-major (w1[o,c] = w1[o*128 + c])
//   b1 : [C]
//   w2 : [C, C]
//   b2 : [C]
// out = x * sigmoid(W2 @ relu(W1 @ max_{dhw}(x) + b1) + b2), gate broadcast per (b,c).

#define BC 1024              // B*C slices
#define SLICE 65536          // D*H*W floats per (b,c)
#define SLICE4 16384         // SLICE / 4

__device__ float d_gp[BC];    // per-(b,c) global max
__device__ float d_gate[BC];  // per-(b,c) sigmoid gate

// ---------------- Kernel 1: per-slice max reduce ----------------
// One block per (b,c) slice. 256 threads, 64 float4 each, coalesced.
// 4 independent accumulator chains to expose MLP to the memory system.
__global__ __launch_bounds__(256) void max_reduce_kernel(const float4* __restrict__ x4) {
    const int bc = blockIdx.x;
    const float4* base = x4 + (size_t)bc * SLICE4;
    const int t = threadIdx.x;

    float m0 = -INFINITY, m1 = -INFINITY, m2 = -INFINITY, m3 = -INFINITY;
    #pragma unroll
    for (int i = 0; i < 16; i++) {
        float4 a = base[t + (4 * i + 0) * 256];
        float4 b = base[t + (4 * i + 1) * 256];
        float4 c = base[t + (4 * i + 2) * 256];
        float4 d = base[t + (4 * i + 3) * 256];
        m0 = fmaxf(m0, fmaxf(fmaxf(a.x, a.y), fmaxf(a.z, a.w)));
        m1 = fmaxf(m1, fmaxf(fmaxf(b.x, b.y), fmaxf(b.z, b.w)));
        m2 = fmaxf(m2, fmaxf(fmaxf(c.x, c.y), fmaxf(c.z, c.w)));
        m3 = fmaxf(m3, fmaxf(fmaxf(d.x, d.y), fmaxf(d.z, d.w)));
    }
    float m = fmaxf(fmaxf(m0, m1), fmaxf(m2, m3));

    // warp reduce
    #pragma unroll
    for (int off = 16; off > 0; off >>= 1)
        m = fmaxf(m, __shfl_xor_sync(0xFFFFFFFFu, m, off));

    __shared__ float s[8];
    if ((t & 31) == 0) s[t >> 5] = m;
    __syncthreads();
    if (t == 0) {
        float r = s[0];
        #pragma unroll
        for (int w = 1; w < 8; w++) r = fmaxf(r, s[w]);
        d_gp[bc] = r;
    }
}

// ---------------- Kernel 2: tiny MLP gate ----------------
// One block, 128 threads (thread = output channel o), all 8 batches.
__global__ __launch_bounds__(128) void mlp_gate_kernel(const float* __restrict__ w1,
                                                       const float* __restrict__ b1,
                                                       const float* __restrict__ w2,
                                                       const float* __restrict__ b2) {
    __shared__ float s_gp[8 * 128];
    __shared__ float s_h[8 * 128];
    const int o = threadIdx.x;

    #pragma unroll
    for (int i = 0; i < 8; i++) s_gp[o + i * 128] = d_gp[o + i * 128];
    __syncthreads();

    // layer 1: h[b,o] = relu(sum_c gp[b,c] * w1[o,c] + b1[o])
    {
        const float* wrow = w1 + o * 128;
        float bias = b1[o];
        #pragma unroll
        for (int b = 0; b < 8; b++) {
            float acc = bias;
            const float* g = s_gp + b * 128;
            #pragma unroll 8
            for (int c = 0; c < 128; c++) acc = fmaf(g[c], wrow[c], acc);
            s_h[b * 128 + o] = fmaxf(acc, 0.0f);
        }
    }
    __syncthreads();

    // layer 2: gate[b,o] = sigmoid(sum_c h[b,c] * w2[o,c] + b2[o])
    {
        const float* wrow = w2 + o * 128;
        float bias = b2[o];
        #pragma unroll
        for (int b = 0; b < 8; b++) {
            float acc = bias;
            const float* h = s_h + b * 128;
            #pragma unroll 8
            for (int c = 0; c < 128; c++) acc = fmaf(h[c], wrow[c], acc);
            d_gate[b * 128 + o] = 1.0f / (1.0f + __expf(-acc));
        }
    }
}

// ---------------- Kernel 3: broadcast scale ----------------
// 16 blocks per (b,c) slice so the gate value is block-uniform.
// 256 threads x 4 float4 = 4096 floats per block; 16*4096 = SLICE.
__global__ __launch_bounds__(256) void scale_kernel(const float4* __restrict__ x4,
                                                    float4* __restrict__ o4) {
    const int blk = blockIdx.x;
    const int bc = blk >> 4;
    const int part = blk & 15;
    const float g = d_gate[bc];

    const size_t off = (size_t)bc * SLICE4 + (size_t)part * 1024;
    const float4* src = x4 + off;
    float4* dst = o4 + off;
    const int t = threadIdx.x;

    #pragma unroll
    for (int i = 0; i < 4; i++) {
        float4 v = src[t + i * 256];
        v.x *= g; v.y *= g; v.z *= g; v.w *= g;
        dst[t + i * 256] = v;
    }
}

extern "C" void kernel_launch(void* const* d_in, const int* in_sizes, int n_in,
                              void* d_out, int out_size) {
    const float* x  = (const float*)d_in[0];
    const float* w1 = (const float*)d_in[1];
    const float* b1 = (const float*)d_in[2];
    const float* w2 = (const float*)d_in[3];
    const float* b2 = (const float*)d_in[4];
    float* out = (float*)d_out;

    max_reduce_kernel<<<BC, 256>>>((const float4*)x);
    mlp_gate_kernel<<<1, 128>>>(w1, b1, w2, b2);
    scale_kernel<<<BC * 16, 256>>>((const float4*)x, (float4*)out);
}

// round 5
// speedup vs baseline: 2.1327x; 2.1327x over previous
#include <cuda_runtime.h>
#include <math.h>

// Shapes (fixed):
//   x  : [B=8, C=128, D=4, H=128, W=128] -> 67,108,864 fp32 (256 MB)
//   w1, w2 : [C, C] row-major (w[o,c] = w[o*128 + c]); b1, b2 : [C]
// out = x * sigmoid(W2 @ relu(W1 @ max_{dhw}(x) + b1) + b2), gate per (b,c).

#define BC 1024              // B*C slices
#define SLICE4 16384         // 65536 floats / 4 per (b,c)
#define C 128
#define CP 129               // padded row for conflict-free smem

__device__ float d_gp[BC];    // per-(b,c) global max
__device__ float d_gate[BC];  // per-(b,c) sigmoid gate

// ---------------- Kernel 1: per-slice max reduce ----------------
// One block per (b,c) slice. 256 threads x 64 float4, coalesced, streaming.
__global__ __launch_bounds__(256) void max_reduce_kernel(const float4* __restrict__ x4) {
    const int bc = blockIdx.x;
    const float4* base = x4 + (size_t)bc * SLICE4;
    const int t = threadIdx.x;

    float m0 = -INFINITY, m1 = -INFINITY, m2 = -INFINITY, m3 = -INFINITY;
    #pragma unroll
    for (int i = 0; i < 16; i++) {
        float4 a = __ldcs(base + t + (4 * i + 0) * 256);
        float4 b = __ldcs(base + t + (4 * i + 1) * 256);
        float4 c = __ldcs(base + t + (4 * i + 2) * 256);
        float4 d = __ldcs(base + t + (4 * i + 3) * 256);
        m0 = fmaxf(m0, fmaxf(fmaxf(a.x, a.y), fmaxf(a.z, a.w)));
        m1 = fmaxf(m1, fmaxf(fmaxf(b.x, b.y), fmaxf(b.z, b.w)));
        m2 = fmaxf(m2, fmaxf(fmaxf(c.x, c.y), fmaxf(c.z, c.w)));
        m3 = fmaxf(m3, fmaxf(fmaxf(d.x, d.y), fmaxf(d.z, d.w)));
    }
    float m = fmaxf(fmaxf(m0, m1), fmaxf(m2, m3));

    #pragma unroll
    for (int off = 16; off > 0; off >>= 1)
        m = fmaxf(m, __shfl_xor_sync(0xFFFFFFFFu, m, off));

    __shared__ float s[8];
    if ((t & 31) == 0) s[t >> 5] = m;
    __syncthreads();
    if (t == 0) {
        float r = s[0];
        #pragma unroll
        for (int w = 1; w < 8; w++) r = fmaxf(r, s[w]);
        d_gp[bc] = r;
    }
}

// ---------------- Kernel 2: tiny MLP gate ----------------
// One block per batch (grid=8), 128 threads (thread = output channel o).
// Weights staged to smem transposed: s_w[c*129 + o] = w[o*128 + c].
//   - global read coalesced (consecutive threads -> consecutive addresses)
//   - STS conflict-free (addr stride 129 across lanes -> distinct banks)
//   - compute LDS conflict-free (fixed c, o across lanes -> consecutive)
__global__ __launch_bounds__(128) void mlp_gate_kernel(const float* __restrict__ w1,
                                                       const float* __restrict__ b1,
                                                       const float* __restrict__ w2,
                                                       const float* __restrict__ b2) {
    __shared__ float s_w1[C * CP];
    __shared__ float s_w2[C * CP];
    __shared__ float s_gp[C];
    __shared__ float s_h[C];

    const int b = blockIdx.x;
    const int o = threadIdx.x;

    // coalesced load + transpose into smem
    #pragma unroll
    for (int i = 0; i < C; i++) {
        int idx = i * 128 + o;          // linear over w (row i, col o) -> coalesced
        int r = idx >> 7;               // source row (output channel)
        int cc = idx & 127;             // source col (input channel)
        s_w1[cc * CP + r] = w1[idx];
        s_w2[cc * CP + r] = w2[idx];
    }
    s_gp[o] = d_gp[b * C + o];
    __syncthreads();

    // layer 1: h[o] = relu(sum_c gp[c] * w1[o,c] + b1[o])
    {
        float a0 = 0.f, a1 = 0.f, a2 = 0.f, a3 = 0.f;
        #pragma unroll
        for (int c = 0; c < C; c += 4) {
            a0 = fmaf(s_gp[c + 0], s_w1[(c + 0) * CP + o], a0);
            a1 = fmaf(s_gp[c + 1], s_w1[(c + 1) * CP + o], a1);
            a2 = fmaf(s_gp[c + 2], s_w1[(c + 2) * CP + o], a2);
            a3 = fmaf(s_gp[c + 3], s_w1[(c + 3) * CP + o], a3);
        }
        s_h[o] = fmaxf((a0 + a1) + (a2 + a3) + b1[o], 0.0f);
    }
    __syncthreads();

    // layer 2: gate[o] = sigmoid(sum_c h[c] * w2[o,c] + b2[o])
    {
        float a0 = 0.f, a1 = 0.f, a2 = 0.f, a3 = 0.f;
        #pragma unroll
        for (int c = 0; c < C; c += 4) {
            a0 = fmaf(s_h[c + 0], s_w2[(c + 0) * CP + o], a0);
            a1 = fmaf(s_h[c + 1], s_w2[(c + 1) * CP + o], a1);
            a2 = fmaf(s_h[c + 2], s_w2[(c + 2) * CP + o], a2);
            a3 = fmaf(s_h[c + 3], s_w2[(c + 3) * CP + o], a3);
        }
        float z = (a0 + a1) + (a2 + a3) + b2[o];
        d_gate[b * C + o] = 1.0f / (1.0f + __expf(-z));
    }
}

// ---------------- Kernel 3: broadcast scale ----------------
// Same shape as the proven reduce kernel: one block per (b,c) slice,
// 256 threads x 64 float4. Streaming loads/stores (no reuse).
__global__ __launch_bounds__(256) void scale_kernel(const float4* __restrict__ x4,
                                                    float4* __restrict__ o4) {
    const int bc = blockIdx.x;
    const float g = d_gate[bc];
    const float4* src = x4 + (size_t)bc * SLICE4;
    float4* dst = o4 + (size_t)bc * SLICE4;
    const int t = threadIdx.x;

    #pragma unroll
    for (int i = 0; i < 64; i++) {
        float4 v = __ldcs(src + t + i * 256);
        v.x *= g; v.y *= g; v.z *= g; v.w *= g;
        __stcs(dst + t + i * 256, v);
    }
}

extern "C" void kernel_launch(void* const* d_in, const int* in_sizes, int n_in,
                              void* d_out, int out_size) {
    const float* x  = (const float*)d_in[0];
    const float* w1 = (const float*)d_in[1];
    const float* b1 = (const float*)d_in[2];
    const float* w2 = (const float*)d_in[3];
    const float* b2 = (const float*)d_in[4];
    float* out = (float*)d_out;

    max_reduce_kernel<<<BC, 256>>>((const float4*)x);
    mlp_gate_kernel<<<8, 128>>>(w1, b1, w2, b2);
    scale_kernel<<<BC, 256>>>((const float4*)x, (float4*)out);
}